// round 17
// baseline (speedup 1.0000x reference)
#include <cuda_runtime.h>
#include <cuda_bf16.h>
#include <cstdint>

// out[b,i,j] = Vx(i; t0,t2) * Vy(j; t1,t2), with
//   t = x @ (W1@W2) + (b1@W2 + b2)   (the two linears collapse)
// Kernel A (latency-optimized): warp per d-row; NO smem stage, NO barrier --
//   each lane loads its W1 float4 + the 12 matching W2 floats (3x float4,
//   contiguous) per chunk; all 16 loads independent -> one DRAM round trip.
// Kernel B: frozen R10 boxcar (warp per row, float4 GEMV __ldcs, STG.64.CS
//   raster) -- measured at ~96% of the HBM write-path ceiling.

#define MAX_D 1024
#define MAX_H 512
#define S 56
#define KSTEEP 10.0f

__device__ float g_w0[MAX_D];
__device__ float g_w1[MAX_D];
__device__ float g_w2[MAX_D];
__device__ float g_beff[3];

// Per-chunk accumulate: v[4c..4c+3] (float4) against W2 rows 4c..4c+3.
// W2 slice = floats W2[12c .. 12c+11], loaded as 3 float4s.
__device__ __forceinline__ void acc_chunk(const float4 v,
                                          const float4 f0, const float4 f1,
                                          const float4 f2,
                                          float& a0, float& a1, float& a2) {
    // f0 = W2[12c+0..3], f1 = W2[12c+4..7], f2 = W2[12c+8..11]
    a0 = fmaf(v.x, f0.x, fmaf(v.y, f0.w, fmaf(v.z, f1.z, fmaf(v.w, f2.y, a0))));
    a1 = fmaf(v.x, f0.y, fmaf(v.y, f1.x, fmaf(v.z, f1.w, fmaf(v.w, f2.z, a1))));
    a2 = fmaf(v.x, f0.z, fmaf(v.y, f1.y, fmaf(v.z, f2.x, fmaf(v.w, f2.w, a2))));
}

// ---------------------------------------------------------------------------
// Kernel A: Weff = W1 @ W2 (warp per d-row), beff = b1 @ W2 + b2 (one warp).
// No smem, no __syncthreads: minimum latency chain.
// ---------------------------------------------------------------------------
__global__ __launch_bounds__(256) void weff_kernel(const float* __restrict__ W1,
                                                   const float* __restrict__ b1,
                                                   const float* __restrict__ W2,
                                                   const float* __restrict__ b2,
                                                   int D, int H) {
    const int lane = threadIdx.x & 31;
    const int warp = (blockIdx.x * blockDim.x + threadIdx.x) >> 5;
    const float4* __restrict__ W24 = (const float4*)W2;
    const int nch = H >> 2;                     // 128 for H=512

    if (warp < D) {
        const float4* __restrict__ row4 = (const float4*)(W1 + (size_t)warp * H);
        float a0 = 0.f, a1 = 0.f, a2 = 0.f;
        #pragma unroll 4
        for (int c = lane; c < nch; c += 32) {
            float4 v  = __ldcs(&row4[c]);       // W1 slice (streaming)
            float4 f0 = W24[3 * c + 0];         // W2 slice: 12 contiguous floats
            float4 f1 = W24[3 * c + 1];
            float4 f2 = W24[3 * c + 2];
            acc_chunk(v, f0, f1, f2, a0, a1, a2);
        }
        #pragma unroll
        for (int o = 16; o > 0; o >>= 1) {
            a0 += __shfl_xor_sync(0xffffffffu, a0, o);
            a1 += __shfl_xor_sync(0xffffffffu, a1, o);
            a2 += __shfl_xor_sync(0xffffffffu, a2, o);
        }
        if (lane == 0) {
            g_w0[warp] = a0;
            g_w1[warp] = a1;
            g_w2[warp] = a2;
        }
    }

    // beff: one warp, identical pattern with b1 as the "row"
    if (blockIdx.x == 0 && threadIdx.x < 32) {
        const float4* __restrict__ b14 = (const float4*)b1;
        float s0 = 0.f, s1 = 0.f, s2 = 0.f;
        #pragma unroll 4
        for (int c = lane; c < nch; c += 32) {
            float4 v  = b14[c];
            float4 f0 = W24[3 * c + 0];
            float4 f1 = W24[3 * c + 1];
            float4 f2 = W24[3 * c + 2];
            acc_chunk(v, f0, f1, f2, s0, s1, s2);
        }
        #pragma unroll
        for (int o = 16; o > 0; o >>= 1) {
            s0 += __shfl_xor_sync(0xffffffffu, s0, o);
            s1 += __shfl_xor_sync(0xffffffffu, s1, o);
            s2 += __shfl_xor_sync(0xffffffffu, s2, o);
        }
        if (lane == 0) {
            g_beff[0] = s0 + b2[0];
            g_beff[1] = s1 + b2[1];
            g_beff[2] = s2 + b2[2];
        }
    }
}

// ---------------------------------------------------------------------------
// Kernel B: one warp per batch row (frozen R10 structure).
// ---------------------------------------------------------------------------
__device__ __forceinline__ float fsigmoid(float z) {
    return 1.0f / (1.0f + __expf(-z));
}

__global__ __launch_bounds__(256) void boxcar_kernel(const float* __restrict__ x,
                                                     float* __restrict__ out,
                                                     int B, int D) {
    __shared__ __align__(16) float s_w0[MAX_D];
    __shared__ __align__(16) float s_w1[MAX_D];
    __shared__ __align__(16) float s_w2[MAX_D];

    for (int e = threadIdx.x; e < D; e += blockDim.x) {
        s_w0[e] = g_w0[e];
        s_w1[e] = g_w1[e];
        s_w2[e] = g_w2[e];
    }
    __syncthreads();

    const int lane = threadIdx.x & 31;
    const int wid  = threadIdx.x >> 5;
    const int row  = blockIdx.x * (blockDim.x >> 5) + wid;
    if (row >= B) return;

    // ---- skinny GEMV, float4-vectorized: 8 LDG.128 + 24 LDS.128 per lane ----
    const float4* __restrict__ x4 = (const float4*)(x + (size_t)row * D);
    const int nch = D >> 2;                     // 256 for D=1024
    float a0 = 0.f, a1 = 0.f, a2 = 0.f;
    #pragma unroll 4
    for (int c = lane; c < nch; c += 32) {
        float4 xv = __ldcs(&x4[c]);             // streaming LDG.128
        int e = c << 2;
        float4 w0 = *(const float4*)&s_w0[e];
        float4 w1 = *(const float4*)&s_w1[e];
        float4 w2 = *(const float4*)&s_w2[e];
        a0 = fmaf(xv.x, w0.x, fmaf(xv.y, w0.y, fmaf(xv.z, w0.z, fmaf(xv.w, w0.w, a0))));
        a1 = fmaf(xv.x, w1.x, fmaf(xv.y, w1.y, fmaf(xv.z, w1.z, fmaf(xv.w, w1.w, a1))));
        a2 = fmaf(xv.x, w2.x, fmaf(xv.y, w2.y, fmaf(xv.z, w2.z, fmaf(xv.w, w2.w, a2))));
    }
    #pragma unroll
    for (int o = 16; o > 0; o >>= 1) {
        a0 += __shfl_xor_sync(0xffffffffu, a0, o);
        a1 += __shfl_xor_sync(0xffffffffu, a1, o);
        a2 += __shfl_xor_sync(0xffffffffu, a2, o);
    }
    const float t0 = a0 + g_beff[0];   // x center (maps to i)
    const float t1 = a1 + g_beff[1];   // y center (maps to j)
    const float t2 = a2 + g_beff[2];   // size

    // ---- boxcar profiles: lane covers coords lane and lane+32 ----
    const float half = 0.5f * t2;
    const float c0 = (float)lane;
    const float c1 = (float)(lane + 32);

    float vx0 = fsigmoid(KSTEEP * (c0 - t0 + half)) - fsigmoid(KSTEEP * (c0 - t0 - half));
    float vy0 = fsigmoid(KSTEEP * (c0 - t1 + half)) - fsigmoid(KSTEEP * (c0 - t1 - half));
    float vx1 = 0.f, vy1 = 0.f;
    if (lane < S - 32) {
        vx1 = fsigmoid(KSTEEP * (c1 - t0 + half)) - fsigmoid(KSTEEP * (c1 - t0 - half));
        vy1 = fsigmoid(KSTEEP * (c1 - t1 + half)) - fsigmoid(KSTEEP * (c1 - t1 - half));
    }

    // ---- gather vy pair for this lane: vy[2*lane], vy[2*lane+1] (lanes 0-27) ----
    const int e_idx = 2 * lane;
    const int o_idx = 2 * lane + 1;
    float eA = __shfl_sync(0xffffffffu, vy0, e_idx & 31);
    float eB = __shfl_sync(0xffffffffu, vy1, e_idx & 31);
    float oA = __shfl_sync(0xffffffffu, vy0, o_idx & 31);
    float oB = __shfl_sync(0xffffffffu, vy1, o_idx & 31);
    const float vyA = (e_idx < 32) ? eA : eB;
    const float vyB = (o_idx < 32) ? oA : oB;

    // ---- rasterize: one STG.64.CS per output row (lanes 0-27) ----
    float2* __restrict__ o2 = (float2*)(out + (size_t)row * (S * S));
    #pragma unroll
    for (int i = 0; i < S; i++) {
        float src = (i < 32) ? vx0 : vx1;
        float vxi = __shfl_sync(0xffffffffu, src, i & 31);
        if (lane < S / 2) {
            float2 r;
            r.x = vxi * vyA;
            r.y = vxi * vyB;
            __stcs(&o2[lane], r);               // evict-first: best measured
        }
        o2 += S / 2;
    }
}

// ---------------------------------------------------------------------------
// Launch. Inputs: x[B,D], W1[D,H], b1[H], W2[H,3], b2[3]. Output: [B,56,56] f32.
// ---------------------------------------------------------------------------
extern "C" void kernel_launch(void* const* d_in, const int* in_sizes, int n_in,
                              void* d_out, int out_size) {
    const float* x  = (const float*)d_in[0];
    const float* W1 = (const float*)d_in[1];
    const float* b1 = (const float*)d_in[2];
    const float* W2 = (const float*)d_in[3];
    const float* b2 = (const float*)d_in[4];
    float* out = (float*)d_out;

    const int H = in_sizes[2];           // 512
    const int D = in_sizes[1] / H;       // 1024
    const int B = in_sizes[0] / D;       // 16384

    {
        int threads = 256;
        int blocks = (D * 32 + threads - 1) / threads;   // warp per d-row
        weff_kernel<<<blocks, threads>>>(W1, b1, W2, b2, D, H);
    }
    {
        int threads = 256;
        int rows_per_block = threads / 32;
        int blocks = (B + rows_per_block - 1) / rows_per_block;
        boxcar_kernel<<<blocks, threads>>>(x, out, B, D);
    }
}